// round 15
// baseline (speedup 1.0000x reference)
#include <cuda_runtime.h>
#include <math.h>

#define B_ 8
#define C_ 64
#define H_ 256
#define W_ 512
#define KF 64
#define NROW (B_*C_*H_)  // 131072 rows

// ---------------- static device scratch (allocation-free rule) ----------------
__device__ __align__(16) float  d_Tce[128 * 32];   // cos(2pi n j/256)        [n][j]
__device__ __align__(16) float  d_Tco[128 * 32];   // cos(pi n (2j+1)/256)    [n][j]
__device__ __align__(16) float  d_Tse[128 * 32];   // -sin(2pi n j/256)       [n][j]
__device__ __align__(16) float  d_Tso[128 * 32];   // -sin(pi n (2j+1)/256)   [n][j]
__device__ __align__(16) float  d_Ipe[32 * 128];   // c2j cos(2pi n j/256)    [j][n]
__device__ __align__(16) float  d_Ipo[32 * 128];   // 2 cos(pi n (2j+1)/256)  [j][n]
__device__ __align__(16) float  d_Iqe[32 * 128];   // c2j sin(2pi n j/256)    [j][n]
__device__ __align__(16) float  d_Iqo[32 * 128];   // 2 sin(pi n (2j+1)/256)  [j][n]
__device__ __align__(16) float2 d_E[W_];           // e^{+2 pi i t/512}
__device__ __align__(16) float  d_xp[(size_t)NROW * KF];
__device__ __align__(16) float2 d_G[B_ * H_ * KF];           // (filt-1)/256
__device__ __align__(16) float  d_U[(size_t)NROW * 2 * KF];  // (b,c,h,k{r,i})
__device__ __align__(16) float  d_V[(size_t)NROW * 2 * KF];  // (b,c,n,k{r,i})

__device__ __forceinline__ float2 cadd(float2 a, float2 b){ return make_float2(a.x+b.x, a.y+b.y); }
__device__ __forceinline__ float2 csub(float2 a, float2 b){ return make_float2(a.x-b.x, a.y-b.y); }
__device__ __forceinline__ float2 cmul(float2 a, float2 b){
    return make_float2(fmaf(a.x,b.x,-a.y*b.y), fmaf(a.x,b.y,a.y*b.x));
}
__device__ __forceinline__ void pf2(const void* p) {
    asm volatile("prefetch.global.L2 [%0];" :: "l"(p));
}

// ---------------- in-register FFT16 (natural order), INV=0 fwd, 1 inv ----------
template<int INV>
__device__ __forceinline__ void fft16(float2* v) {
    const float C1 = 0.9238795325112867f, S1 = 0.3826834323650898f;
    const float C2 = 0.7071067811865476f;
    const float sg = INV ? 1.f : -1.f;
    const float2 w1 = make_float2( C1, sg*S1);
    const float2 w2 = make_float2( C2, sg*C2);
    const float2 w3 = make_float2( S1, sg*C1);
    const float2 w4 = make_float2(0.f, sg);
    const float2 w6 = make_float2(-C2, sg*C2);
    const float2 w9 = make_float2(-C1, -sg*S1);
    float2 A[16];
#pragma unroll
    for (int n0 = 0; n0 < 4; n0++) {
        float2 a=v[n0], b=v[n0+4], c=v[n0+8], d=v[n0+12];
        float2 t0=cadd(a,c), t1=csub(a,c), t2=cadd(b,d), t3=csub(b,d);
        float2 jt3 = INV ? make_float2(-t3.y, t3.x) : make_float2(t3.y, -t3.x);
        A[n0*4+0]=cadd(t0,t2); A[n0*4+1]=cadd(t1,jt3);
        A[n0*4+2]=csub(t0,t2); A[n0*4+3]=csub(t1,jt3);
    }
    A[5]=cmul(A[5],w1);  A[6]=cmul(A[6],w2);  A[7]=cmul(A[7],w3);
    A[9]=cmul(A[9],w2);  A[10]=cmul(A[10],w4); A[11]=cmul(A[11],w6);
    A[13]=cmul(A[13],w3); A[14]=cmul(A[14],w6); A[15]=cmul(A[15],w9);
#pragma unroll
    for (int k1 = 0; k1 < 4; k1++) {
        float2 a=A[k1], b=A[4+k1], c=A[8+k1], d=A[12+k1];
        float2 t0=cadd(a,c), t1=csub(a,c), t2=cadd(b,d), t3=csub(b,d);
        float2 jt3 = INV ? make_float2(-t3.y, t3.x) : make_float2(t3.y, -t3.x);
        v[k1+0]=cadd(t0,t2); v[k1+4]=cadd(t1,jt3);
        v[k1+8]=csub(t0,t2); v[k1+12]=csub(t1,jt3);
    }
}

// ---------------- tables (float sincospif: args are exact m/256) ----------------
__global__ void k_tables() {
    int t = blockIdx.x * 256 + threadIdx.x;     // 32768
    if (t < 512) {
        float s, c; sincospif((float)t / 256.f, &s, &c);
        d_E[t] = make_float2(c, s);
    }
    int id = t >> 12, idx = t & 4095;
    float s, c;
    if (id < 4) {                               // fwd: idx = n*32 + j
        int n = idx >> 5, j = idx & 31;
        if (id == 0 || id == 2) sincospif((float)((n * j) & 255) / 128.f, &s, &c);
        else                    sincospif((float)((n * (2 * j + 1)) & 511) / 256.f, &s, &c);
        if (id == 0) d_Tce[idx] = c;
        else if (id == 1) d_Tco[idx] = c;
        else if (id == 2) d_Tse[idx] = -s;
        else              d_Tso[idx] = -s;
    } else {                                    // inv: idx = j*128 + n
        int j = idx >> 7, n = idx & 127;
        if (id == 4 || id == 6) sincospif((float)((n * j) & 255) / 128.f, &s, &c);
        else                    sincospif((float)((n * (2 * j + 1)) & 511) / 256.f, &s, &c);
        float ce = (j == 0) ? 1.f : 2.f;
        if (id == 4) d_Ipe[idx] = ce * c;
        else if (id == 5) d_Ipo[idx] = 2.f * c;
        else if (id == 6) d_Iqe[idx] = ce * s;
        else              d_Iqo[idx] = 2.f * s;
    }
}

// ---------------- K1 forward: plane-split groups, 128 rows/block ----------------
__global__ void __launch_bounds__(256) k_fwd(const float* __restrict__ x) {
    __shared__ float SEp[16][132], SEm[16][132], SOm[16][132], SOp[16][132];
    __shared__ float SCe[16][32], SCo[16][32], SSe[16][32], SSo[16][32];
    const int tid = threadIdx.x;
    const long row0 = (long)blockIdx.x * 128;
    const int grp = tid >> 7;           // 0: even k (re_e,im_e), 1: odd k
    const int idx = tid & 127;
    const int rg  = idx >> 3;           // 16 row groups x 8 rows
    const int cg  = idx & 7;            // 8 col groups x 4 j

    float aR[8][4], aI[8][4];
#pragma unroll
    for (int m = 0; m < 8; m++)
#pragma unroll
        for (int w = 0; w < 4; w++) { aR[m][w] = 0.f; aI[m][w] = 0.f; }

    const int r = tid >> 1;             // 0..127 row for A-phase
    const int half = tid & 1;
    const float* xp = x + (row0 + r) * W_;
    float* xpr = d_xp + (row0 + r) * 64;

    for (int kc = 0; kc < 128; kc += 16) {
        __syncthreads();
        {   // A-phase fold + fused pooling (8-aligned, no shuffles)
            int o = kc + half * 8;
            float4 a0 = *(const float4*)(xp + o);
            float4 a1 = *(const float4*)(xp + o + 4);
            float4 c0 = *(const float4*)(xp + 256 + o);
            float4 c1 = *(const float4*)(xp + 260 + o);
            float4 bl = *(const float4*)(xp + 248 - o);
            float4 bh = *(const float4*)(xp + 252 - o);
            float4 dl = *(const float4*)(xp + 504 - o);
            float4 dh = *(const float4*)(xp + 508 - o);
            float  bsc = xp[256 - o];
            float  dsc = xp[(512 - o) & 511];
            int g = o >> 3;
            xpr[g]      = ((a0.x+a0.y)+(a0.z+a0.w)+(a1.x+a1.y)+(a1.z+a1.w))*0.125f;
            xpr[31 - g] = ((bl.x+bl.y)+(bl.z+bl.w)+(bh.x+bh.y)+(bh.z+bh.w))*0.125f;
            xpr[32 + g] = ((c0.x+c0.y)+(c0.z+c0.w)+(c1.x+c1.y)+(c1.z+c1.w))*0.125f;
            xpr[63 - g] = ((dl.x+dl.y)+(dl.z+dl.w)+(dh.x+dh.y)+(dh.z+dh.w))*0.125f;
            float aq[8] = {a0.x,a0.y,a0.z,a0.w,a1.x,a1.y,a1.z,a1.w};
            float cq[8] = {c0.x,c0.y,c0.z,c0.w,c1.x,c1.y,c1.z,c1.w};
            float bq[8] = {bsc,bh.w,bh.z,bh.y,bh.x,bl.w,bl.z,bl.y};
            float dq[8] = {dsc,dh.w,dh.z,dh.y,dh.x,dl.w,dl.z,dl.y};
            int jb = half * 8;
#pragma unroll
            for (int q = 0; q < 8; q++) {
                float sa = aq[q] + dq[q], da = aq[q] - dq[q];
                float sb = bq[q] + cq[q], db = bq[q] - cq[q];
                float ep = sa + sb, em = sa - sb, om = da - db, op = da + db;
                if (o + q == 0) { ep = 0.f; em = 0.f; om = 0.f; op = 0.f; }
                SEp[jb + q][r] = ep; SEm[jb + q][r] = em;
                SOm[jb + q][r] = om; SOp[jb + q][r] = op;
            }
        }
#pragma unroll
        for (int i = 0; i < 2; i++) {   // B tiles: 512 float4
            int f = tid + i * 256;
            int which = f >> 7, gg = f & 127;
            int nl = gg >> 3, c4 = (gg & 7) * 4;
            const float* src =
                (which == 0 ? d_Tce : which == 1 ? d_Tco : which == 2 ? d_Tse : d_Tso)
                + (kc + nl) * 32 + c4;
            float* dst = (which == 0 ? &SCe[nl][c4] : which == 1 ? &SCo[nl][c4]
                        : which == 2 ? &SSe[nl][c4] : &SSo[nl][c4]);
            *(float4*)dst = *(const float4*)src;
        }
        __syncthreads();
        // L2 prefetch: next chunk's A segments (or epilogue scalars on last chunk)
        if (kc < 112) {
            int o2 = kc + 16 + half * 8;
            pf2(xp + o2);       pf2(xp + 256 + o2);
            pf2(xp + 248 - o2); pf2(xp + 504 - o2);
        } else {
#pragma unroll
            for (int m = 0; m < 8; m++) {
                const float* xr = x + (row0 + rg * 8 + m) * W_;
                pf2(xr); pf2(xr + 128); pf2(xr + 256); pf2(xr + 384);
            }
        }
        const float* Ap = grp ? &SEm[0][0] : &SEp[0][0];
        const float* Ai = grp ? &SOp[0][0] : &SOm[0][0];
        const float* Bc = grp ? &SCo[0][0] : &SCe[0][0];
        const float* Bs = grp ? &SSo[0][0] : &SSe[0][0];
#pragma unroll
        for (int nl = 0; nl < 16; nl++) {
            float4 e0 = *(const float4*)(Ap + nl * 132 + rg * 8);
            float4 e1 = *(const float4*)(Ap + nl * 132 + rg * 8 + 4);
            float4 q0 = *(const float4*)(Ai + nl * 132 + rg * 8);
            float4 q1 = *(const float4*)(Ai + nl * 132 + rg * 8 + 4);
            float4 bc = *(const float4*)(Bc + nl * 32 + cg * 4);
            float4 bs = *(const float4*)(Bs + nl * 32 + cg * 4);
            float ev[8] = {e0.x,e0.y,e0.z,e0.w,e1.x,e1.y,e1.z,e1.w};
            float ov[8] = {q0.x,q0.y,q0.z,q0.w,q1.x,q1.y,q1.z,q1.w};
            float bcv[4] = {bc.x,bc.y,bc.z,bc.w};
            float bsv[4] = {bs.x,bs.y,bs.z,bs.w};
#pragma unroll
            for (int m = 0; m < 8; m++)
#pragma unroll
                for (int w = 0; w < 4; w++) {
                    aR[m][w] = fmaf(ev[m], bcv[w], aR[m][w]);
                    aI[m][w] = fmaf(ov[m], bsv[w], aI[m][w]);
                }
        }
    }
    // epilogue: boundary terms; float2 (re,im) stores
#pragma unroll
    for (int m = 0; m < 8; m++) {
        long row = row0 + rg * 8 + m;
        const float* xr = x + row * W_;
        float x0 = xr[0], x128 = xr[128], x256 = xr[256], x384 = xr[384];
        float e128 = x128 + x384, o128 = x128 - x384;
        float* Up = d_U + row * 128 + (grp ? 2 : 0);
#pragma unroll
        for (int w = 0; w < 4; w++) {
            int j = cg * 4 + w;
            float re, im;
            if (!grp) {
                re = aR[m][w] + x0 + x256 + ((j & 1) ? -e128 : e128);
                im = aI[m][w];
            } else {
                re = aR[m][w] + x0 - x256;
                im = aI[m][w] + ((j & 1) ? o128 : -o128);
            }
            *(float2*)(Up + 4 * j) = make_float2(re, im);
        }
    }
}

// ---------------- filter (fast-math, float4 LDS) ----------------
__global__ void __launch_bounds__(256) k_filter(
    const float* __restrict__ w, const float* __restrict__ bias,
    const float* __restrict__ dt)
{
    __shared__ float ws[4096];
    __shared__ float bs[64];
    int tid = threadIdx.x;
#pragma unroll
    for (int i = tid; i < 4096; i += 256) ws[i] = w[i];
    if (tid < 64) bs[tid] = bias[tid];
    __syncthreads();

    int id = blockIdx.x * 256 + tid;
    int j = id & 63, h = (id >> 6) & 255, bb = id >> 14;
    float xv[64];
#pragma unroll
    for (int c = 0; c < 64; c++)
        xv[c] = d_xp[(((size_t)(bb * 64 + c)) * 256 + h) * 64 + j];
    float dtb = dt[bb];
    float pdt = 3.14159265358979323846f * dtb;
    float fr = 0.f, fi = 0.f;
    for (int r = 0; r < 32; r++) {
        float p1 = bs[r], p2 = bs[32 + r];
#pragma unroll
        for (int c4 = 0; c4 < 16; c4++) {
            float4 w1 = *(const float4*)&ws[r * 64 + c4 * 4];
            float4 w2 = *(const float4*)&ws[(32 + r) * 64 + c4 * 4];
            p1 = fmaf(w1.x, xv[c4*4+0], p1); p2 = fmaf(w2.x, xv[c4*4+0], p2);
            p1 = fmaf(w1.y, xv[c4*4+1], p1); p2 = fmaf(w2.y, xv[c4*4+1], p2);
            p1 = fmaf(w1.z, xv[c4*4+2], p1); p2 = fmaf(w2.z, xv[c4*4+2], p2);
            p1 = fmaf(w1.w, xv[c4*4+3], p1); p2 = fmaf(w2.w, xv[c4*4+3], p2);
        }
        float nu  = __logf(1.f + __expf(p1));
        float e2  = __expf(2.f * p2);
        float ang = pdt - __fdividef(2.f * pdt, e2 + 1.f);
        float dec = __expf(-nu * dtb);
        float s, co; __sincosf(ang, &s, &co);
        fr = fmaf(dec, co, fr);
        fi = fmaf(dec, s, fi);
    }
    d_G[id] = make_float2((fr - 1.f) * 0.00390625f, fi * 0.00390625f);
}

// ---------------- fused H transform (in-place smem, 20.5KB) ----------------
#define PSTR 9
__global__ void __launch_bounds__(128) k_hfft() {
    __shared__ float SAr[256*PSTR], SAi[256*PSTR];
    __shared__ float2 Ws[256];
    const int bc = blockIdx.x >> 1;
    const int half = blockIdx.x & 1;
    const int b = bc >> 6;
    const int t = threadIdx.x;
    const int kk = t & 7, u = t >> 3;

    for (int i = t; i < 256; i += 128) {
        float2 e = d_E[2 * i];
        Ws[i] = make_float2(e.x, -e.y);
    }
    const float2* Ub = (const float2*)d_U + (size_t)bc * 256 * 64;
    float2*       Vb = (float2*)d_V + (size_t)bc * 256 * 64;

    for (int kb = half * 32; kb < half * 32 + 32; kb += 8) {
        __syncthreads();                    // guard: prev phase-C reads done
        for (int i = t; i < 2048; i += 128) {
            int h = i >> 3, k2 = i & 7;
            float2 uv = Ub[h * 64 + kb + k2];
            SAr[h * PSTR + k2] = uv.x; SAi[h * PSTR + k2] = uv.y;
        }
        __syncthreads();
        float2 v[16];
        // phase A: fwd over n2, in-place transpose via regs
#pragma unroll
        for (int n2 = 0; n2 < 16; n2++) {
            int p = (u + 16 * n2) * PSTR + kk;
            v[n2] = make_float2(SAr[p], SAi[p]);
        }
        fft16<0>(v);
#pragma unroll
        for (int k2 = 1; k2 < 16; k2++) v[k2] = cmul(v[k2], Ws[u * k2]);
        __syncthreads();                    // all reads done before overwrite
#pragma unroll
        for (int k2 = 0; k2 < 16; k2++) {
            int p = (k2 * 16 + u) * PSTR + kk;
            SAr[p] = v[k2].x; SAi[p] = v[k2].y;
        }
        __syncthreads();
        // phase B: fwd stage-2, xG, inv stage-1
#pragma unroll
        for (int n1 = 0; n1 < 16; n1++) {
            int p = (u * 16 + n1) * PSTR + kk;
            v[n1] = make_float2(SAr[p], SAi[p]);
        }
        fft16<0>(v);
#pragma unroll
        for (int r = 0; r < 16; r++) {
            float2 g = d_G[((size_t)b * 256 + u + 16 * r) * 64 + kb + kk];
            v[r] = cmul(v[r], g);
        }
        fft16<1>(v);
        __syncthreads();
#pragma unroll
        for (int n2 = 0; n2 < 16; n2++) {
            float2 wc = Ws[u * n2]; wc.y = -wc.y;
            float2 r = cmul(v[n2], wc);
            int p = (n2 * 16 + u) * PSTR + kk;
            SAr[p] = r.x; SAi[p] = r.y;
        }
        __syncthreads();
        // phase C: inv stage-2, write out
#pragma unroll
        for (int m1 = 0; m1 < 16; m1++) {
            int p = (u * 16 + m1) * PSTR + kk;
            v[m1] = make_float2(SAr[p], SAi[p]);
        }
        fft16<1>(v);
#pragma unroll
        for (int n1 = 0; n1 < 16; n1++)
            Vb[(u + 16 * n1) * 64 + kb + kk] = v[n1];
    }
}

// ---------------- K5 inverse: plane-split + single exchange + fused edge --------
__global__ void __launch_bounds__(256) k_inv(const float* __restrict__ x,
                                             float* __restrict__ out) {
    __shared__ float SM[8960];
    float* VRe = SM;            float* VIe = SM + 1088;
    float* VRo = SM + 2176;     float* VIo = SM + 3264;
    float* BPe = SM + 4352;     float* BPo = SM + 5376;
    float* BQe = SM + 6400;     float* BQo = SM + 7424;
    const int tid = threadIdx.x;
    const int grp = tid >> 7;           // 0: (Pe,Qe)  1: (Po,Qo)
    const int idx = tid & 127;
    const int rg  = idx >> 4;           // 8 row groups x 8 rows
    const int ng  = idx & 15;           // 16 n groups x 4 n
    const long row0 = (long)blockIdx.x * 64;
    const int n0 = blockIdx.y * 64;
    const bool edge = (grp == 0) && (ng == 0) && (n0 == 0);

    float P[8][4], Q[8][4];
    float P128[8], Q128[8];
#pragma unroll
    for (int m = 0; m < 8; m++) {
        P128[m] = 0.f; Q128[m] = 0.f;
#pragma unroll
        for (int w = 0; w < 4; w++) { P[m][w] = 0.f; Q[m][w] = 0.f; }
    }

    for (int jc = 0; jc < 32; jc += 16) {
        __syncthreads();
#pragma unroll
        for (int i = 0; i < 4; i++) {   // V chunk -> 4 planes
            int f = tid + i * 256;
            int r = f >> 4, jl = f & 15;
            float4 v = *(const float4*)&d_V[(row0 + r) * 128 + (jc + jl) * 4];
            VRe[jl * 68 + r] = v.x; VIe[jl * 68 + r] = v.y;
            VRo[jl * 68 + r] = v.z; VIo[jl * 68 + r] = v.w;
        }
#pragma unroll
        for (int i = 0; i < 4; i++) {   // B tables
            int f = tid + i * 256;
            int which = f >> 8, gg = f & 255;
            int jl = gg >> 4, n4 = (gg & 15) * 4;
            const float* src =
                (which == 0 ? d_Ipe : which == 1 ? d_Ipo : which == 2 ? d_Iqe : d_Iqo)
                + (jc + jl) * 128 + n0 + n4;
            float* dst = (which == 0 ? BPe : which == 1 ? BPo
                        : which == 2 ? BQe : BQo) + jl * 64 + n4;
            *(float4*)dst = *(const float4*)src;
        }
        __syncthreads();
        // L2 prefetch: next V chunk, or epilogue x lines on last chunk
        if (jc == 0) {
#pragma unroll
            for (int i = 0; i < 4; i++) {
                int f = tid + i * 256;
                pf2(&d_V[(row0 + (f >> 4)) * 128 + (16 + (f & 15)) * 4]);
            }
        } else if (!grp) {
            const int nn0p = n0 + ng * 4;
#pragma unroll
            for (int m = 0; m < 8; m++) {
                const float* xr = x + (row0 + rg * 8 + m) * W_;
                pf2(xr + nn0p);       pf2(xr + 256 + nn0p);
                pf2(xr + 253 - nn0p); pf2(xr + 506 - nn0p);
            }
        }
        const float* Vr = grp ? VRo : VRe;
        const float* Vi = grp ? VIo : VIe;
        const float* Bp = grp ? BPo : BPe;
        const float* Bq = grp ? BQo : BQe;
#pragma unroll
        for (int jl = 0; jl < 16; jl++) {
            float4 r0 = *(const float4*)(Vr + jl * 68 + rg * 8);
            float4 r1 = *(const float4*)(Vr + jl * 68 + rg * 8 + 4);
            float4 i0 = *(const float4*)(Vi + jl * 68 + rg * 8);
            float4 i1 = *(const float4*)(Vi + jl * 68 + rg * 8 + 4);
            float4 bp = *(const float4*)(Bp + jl * 64 + ng * 4);
            float4 bq = *(const float4*)(Bq + jl * 64 + ng * 4);
            float vr[8] = {r0.x,r0.y,r0.z,r0.w,r1.x,r1.y,r1.z,r1.w};
            float vi[8] = {i0.x,i0.y,i0.z,i0.w,i1.x,i1.y,i1.z,i1.w};
            float pv[4] = {bp.x,bp.y,bp.z,bp.w};
            float qv[4] = {bq.x,bq.y,bq.z,bq.w};
#pragma unroll
            for (int m = 0; m < 8; m++)
#pragma unroll
                for (int w = 0; w < 4; w++) {
                    P[m][w] = fmaf(vr[m], pv[w], P[m][w]);
                    Q[m][w] = fmaf(vi[m], qv[w], Q[m][w]);
                }
        }
        // fused edge columns: n=128 weights (odd-cos & even-sin vanish)
        if (edge) {
            for (int jl = 0; jl < 16; jl++) {
                int j = jc + jl;
                float wE = (j == 0) ? 1.f : ((j & 1) ? -2.f : 2.f);
                float wO = (j & 1) ? -2.f : 2.f;
#pragma unroll
                for (int m = 0; m < 8; m++) {
                    P128[m] = fmaf(VRe[jl * 68 + rg * 8 + m], wE, P128[m]);
                    Q128[m] = fmaf(VIo[jl * 68 + rg * 8 + m], wO, Q128[m]);
                }
            }
        }
    }
    __syncthreads();
    if (grp) {                          // O group ships P,Q through smem
        float* e = SM + idx * 70;
#pragma unroll
        for (int m = 0; m < 8; m++)
#pragma unroll
            for (int w = 0; w < 4; w++) {
                e[m * 4 + w]      = P[m][w];
                e[32 + m * 4 + w] = Q[m][w];
            }
    }
    __syncthreads();
    if (!grp) {                         // E group combines + stores everything
        const float* e = SM + idx * 70;
        const float s = 1.f / 512.f;
#pragma unroll
        for (int m = 0; m < 8; m++) {
            long row = row0 + rg * 8 + m;
            const float* xr = x + row * W_;
            float* orow = out + row * W_;
            int nn0 = n0 + ng * 4;
            float4 xf = *(const float4*)(xr + nn0);
            float4 xg = *(const float4*)(xr + 256 + nn0);
            float d1[4], d2[4], d3[4], d4[4];
#pragma unroll
            for (int w = 0; w < 4; w++) {
                float Po = e[m * 4 + w], Qo = e[32 + m * 4 + w];
                float pp = P[m][w] + Po, pm = P[m][w] - Po;
                float qp = Q[m][w] + Qo, qm = Q[m][w] - Qo;
                d1[w] = pp - qp;    // y[n]
                d2[w] = pp + qp;    // y[512-n]
                d3[w] = pm + qm;    // y[256-n]
                d4[w] = pm - qm;    // y[256+n]
            }
            float4 o1, o2;
            o1.x = fmaf(d1[0], s, xf.x); o1.y = fmaf(d1[1], s, xf.y);
            o1.z = fmaf(d1[2], s, xf.z); o1.w = fmaf(d1[3], s, xf.w);
            o2.x = fmaf(d4[0], s, xg.x); o2.y = fmaf(d4[1], s, xg.y);
            o2.z = fmaf(d4[2], s, xg.z); o2.w = fmaf(d4[3], s, xg.w);
            *(float4*)(orow + nn0) = o1;
            *(float4*)(orow + 256 + nn0) = o2;
            {   // mirror 256-n  (range [129,256])
                int b0 = 256 - nn0;
                orow[b0] = fmaf(d3[0], s, xr[b0]);
                float2 mm = *(const float2*)(xr + b0 - 2);
                *(float2*)(orow + b0 - 2) =
                    make_float2(fmaf(d3[2], s, mm.x), fmaf(d3[1], s, mm.y));
                orow[b0 - 3] = fmaf(d3[3], s, xr[b0 - 3]);
            }
            {   // mirror (512-n)&511 (wrap at nn0=0,w=0 writes same value as o1.x)
                int b0 = (512 - nn0) & 511;
                orow[b0] = fmaf(d2[0], s, xr[b0]);
                int b2 = 510 - nn0;
                float2 mm = *(const float2*)(xr + b2);
                *(float2*)(orow + b2) =
                    make_float2(fmaf(d2[2], s, mm.x), fmaf(d2[1], s, mm.y));
                orow[b2 - 1] = fmaf(d2[3], s, xr[b2 - 1]);
            }
            if (edge) {     // columns 128 & 384 (only n0==0, ng==0 threads)
                out[row * W_ + 128] = fmaf(P128[m] - Q128[m], s, xr[128]);
                out[row * W_ + 384] = fmaf(P128[m] + Q128[m], s, xr[384]);
            }
        }
    }
}

// ---------------- launch ----------------
extern "C" void kernel_launch(void* const* d_in, const int* in_sizes, int n_in,
                              void* d_out, int out_size) {
    const float* x    = (const float*)d_in[0];
    const float* dt   = (const float*)d_in[1];
    const float* w    = (const float*)d_in[2];
    const float* bias = (const float*)d_in[3];
    float* out = (float*)d_out;

    k_tables<<<128, 256>>>();
    k_fwd<<<NROW / 128, 256>>>(x);      // also writes d_xp (fused pooling)
    k_filter<<<B_ * H_ * KF / 256, 256>>>(w, bias, dt);
    k_hfft<<<B_ * C_ * 2, 128>>>();
    k_inv<<<dim3(NROW / 64, 2), 256>>>(x, out);
}

// round 16
// speedup vs baseline: 1.0332x; 1.0332x over previous
#include <cuda_runtime.h>
#include <math.h>

#define B_ 8
#define C_ 64
#define H_ 256
#define W_ 512
#define KF 64
#define NROW (B_*C_*H_)  // 131072 rows

// ---------------- static device scratch (allocation-free rule) ----------------
__device__ __align__(16) float  d_Tce[128 * 32];   // cos(2pi n j/256)        [n][j]
__device__ __align__(16) float  d_Tco[128 * 32];   // cos(pi n (2j+1)/256)    [n][j]
__device__ __align__(16) float  d_Tse[128 * 32];   // -sin(2pi n j/256)       [n][j]
__device__ __align__(16) float  d_Tso[128 * 32];   // -sin(pi n (2j+1)/256)   [n][j]
__device__ __align__(16) float  d_Ipe[32 * 128];   // c2j cos(2pi n j/256)    [j][n]
__device__ __align__(16) float  d_Ipo[32 * 128];   // 2 cos(pi n (2j+1)/256)  [j][n]
__device__ __align__(16) float  d_Iqe[32 * 128];   // c2j sin(2pi n j/256)    [j][n]
__device__ __align__(16) float  d_Iqo[32 * 128];   // 2 sin(pi n (2j+1)/256)  [j][n]
__device__ __align__(16) float2 d_E[W_];           // e^{+2 pi i t/512}
__device__ __align__(16) float  d_xp[(size_t)NROW * KF];
__device__ __align__(16) float2 d_G[B_ * H_ * KF];           // (filt-1)/256
__device__ __align__(16) float  d_U[(size_t)NROW * 2 * KF];  // (b,c,h,k{r,i})
__device__ __align__(16) float  d_V[(size_t)NROW * 2 * KF];  // (b,c,n,k{r,i})

__device__ __forceinline__ float2 cadd(float2 a, float2 b){ return make_float2(a.x+b.x, a.y+b.y); }
__device__ __forceinline__ float2 csub(float2 a, float2 b){ return make_float2(a.x-b.x, a.y-b.y); }
__device__ __forceinline__ float2 cmul(float2 a, float2 b){
    return make_float2(fmaf(a.x,b.x,-a.y*b.y), fmaf(a.x,b.y,a.y*b.x));
}

// ---------------- in-register FFT16 (natural order), INV=0 fwd, 1 inv ----------
template<int INV>
__device__ __forceinline__ void fft16(float2* v) {
    const float C1 = 0.9238795325112867f, S1 = 0.3826834323650898f;
    const float C2 = 0.7071067811865476f;
    const float sg = INV ? 1.f : -1.f;
    const float2 w1 = make_float2( C1, sg*S1);
    const float2 w2 = make_float2( C2, sg*C2);
    const float2 w3 = make_float2( S1, sg*C1);
    const float2 w4 = make_float2(0.f, sg);
    const float2 w6 = make_float2(-C2, sg*C2);
    const float2 w9 = make_float2(-C1, -sg*S1);
    float2 A[16];
#pragma unroll
    for (int n0 = 0; n0 < 4; n0++) {
        float2 a=v[n0], b=v[n0+4], c=v[n0+8], d=v[n0+12];
        float2 t0=cadd(a,c), t1=csub(a,c), t2=cadd(b,d), t3=csub(b,d);
        float2 jt3 = INV ? make_float2(-t3.y, t3.x) : make_float2(t3.y, -t3.x);
        A[n0*4+0]=cadd(t0,t2); A[n0*4+1]=cadd(t1,jt3);
        A[n0*4+2]=csub(t0,t2); A[n0*4+3]=csub(t1,jt3);
    }
    A[5]=cmul(A[5],w1);  A[6]=cmul(A[6],w2);  A[7]=cmul(A[7],w3);
    A[9]=cmul(A[9],w2);  A[10]=cmul(A[10],w4); A[11]=cmul(A[11],w6);
    A[13]=cmul(A[13],w3); A[14]=cmul(A[14],w6); A[15]=cmul(A[15],w9);
#pragma unroll
    for (int k1 = 0; k1 < 4; k1++) {
        float2 a=A[k1], b=A[4+k1], c=A[8+k1], d=A[12+k1];
        float2 t0=cadd(a,c), t1=csub(a,c), t2=cadd(b,d), t3=csub(b,d);
        float2 jt3 = INV ? make_float2(-t3.y, t3.x) : make_float2(t3.y, -t3.x);
        v[k1+0]=cadd(t0,t2); v[k1+4]=cadd(t1,jt3);
        v[k1+8]=csub(t0,t2); v[k1+12]=csub(t1,jt3);
    }
}

// ---------------- tables (float sincospif: args are exact m/256) ----------------
__global__ void k_tables() {
    int t = blockIdx.x * 256 + threadIdx.x;     // 32768
    if (t < 512) {
        float s, c; sincospif((float)t / 256.f, &s, &c);
        d_E[t] = make_float2(c, s);
    }
    int id = t >> 12, idx = t & 4095;
    float s, c;
    if (id < 4) {                               // fwd: idx = n*32 + j
        int n = idx >> 5, j = idx & 31;
        if (id == 0 || id == 2) sincospif((float)((n * j) & 255) / 128.f, &s, &c);
        else                    sincospif((float)((n * (2 * j + 1)) & 511) / 256.f, &s, &c);
        if (id == 0) d_Tce[idx] = c;
        else if (id == 1) d_Tco[idx] = c;
        else if (id == 2) d_Tse[idx] = -s;
        else              d_Tso[idx] = -s;
    } else {                                    // inv: idx = j*128 + n
        int j = idx >> 7, n = idx & 127;
        if (id == 4 || id == 6) sincospif((float)((n * j) & 255) / 128.f, &s, &c);
        else                    sincospif((float)((n * (2 * j + 1)) & 511) / 256.f, &s, &c);
        float ce = (j == 0) ? 1.f : 2.f;
        if (id == 4) d_Ipe[idx] = ce * c;
        else if (id == 5) d_Ipo[idx] = 2.f * c;
        else if (id == 6) d_Iqe[idx] = ce * s;
        else              d_Iqo[idx] = 2.f * s;
    }
}

// ---------------- K1 forward: plane-split groups, 128 rows/block ----------------
__global__ void __launch_bounds__(256) k_fwd(const float* __restrict__ x) {
    __shared__ float SEp[16][132], SEm[16][132], SOm[16][132], SOp[16][132];
    __shared__ float SCe[16][32], SCo[16][32], SSe[16][32], SSo[16][32];
    const int tid = threadIdx.x;
    const long row0 = (long)blockIdx.x * 128;
    const int grp = tid >> 7;           // 0: even k (re_e,im_e), 1: odd k
    const int idx = tid & 127;
    const int rg  = idx >> 3;           // 16 row groups x 8 rows
    const int cg  = idx & 7;            // 8 col groups x 4 j

    float aR[8][4], aI[8][4];
#pragma unroll
    for (int m = 0; m < 8; m++)
#pragma unroll
        for (int w = 0; w < 4; w++) { aR[m][w] = 0.f; aI[m][w] = 0.f; }

    const int r = tid >> 1;             // 0..127 row for A-phase
    const int half = tid & 1;
    const float* xp = x + (row0 + r) * W_;
    float* xpr = d_xp + (row0 + r) * 64;

    for (int kc = 0; kc < 128; kc += 16) {
        __syncthreads();
        {   // A-phase fold + fused pooling (8-aligned, no shuffles)
            int o = kc + half * 8;
            float4 a0 = *(const float4*)(xp + o);
            float4 a1 = *(const float4*)(xp + o + 4);
            float4 c0 = *(const float4*)(xp + 256 + o);
            float4 c1 = *(const float4*)(xp + 260 + o);
            float4 bl = *(const float4*)(xp + 248 - o);
            float4 bh = *(const float4*)(xp + 252 - o);
            float4 dl = *(const float4*)(xp + 504 - o);
            float4 dh = *(const float4*)(xp + 508 - o);
            float  bsc = xp[256 - o];
            float  dsc = xp[(512 - o) & 511];
            int g = o >> 3;
            xpr[g]      = ((a0.x+a0.y)+(a0.z+a0.w)+(a1.x+a1.y)+(a1.z+a1.w))*0.125f;
            xpr[31 - g] = ((bl.x+bl.y)+(bl.z+bl.w)+(bh.x+bh.y)+(bh.z+bh.w))*0.125f;
            xpr[32 + g] = ((c0.x+c0.y)+(c0.z+c0.w)+(c1.x+c1.y)+(c1.z+c1.w))*0.125f;
            xpr[63 - g] = ((dl.x+dl.y)+(dl.z+dl.w)+(dh.x+dh.y)+(dh.z+dh.w))*0.125f;
            float aq[8] = {a0.x,a0.y,a0.z,a0.w,a1.x,a1.y,a1.z,a1.w};
            float cq[8] = {c0.x,c0.y,c0.z,c0.w,c1.x,c1.y,c1.z,c1.w};
            float bq[8] = {bsc,bh.w,bh.z,bh.y,bh.x,bl.w,bl.z,bl.y};
            float dq[8] = {dsc,dh.w,dh.z,dh.y,dh.x,dl.w,dl.z,dl.y};
            int jb = half * 8;
#pragma unroll
            for (int q = 0; q < 8; q++) {
                float sa = aq[q] + dq[q], da = aq[q] - dq[q];
                float sb = bq[q] + cq[q], db = bq[q] - cq[q];
                float ep = sa + sb, em = sa - sb, om = da - db, op = da + db;
                if (o + q == 0) { ep = 0.f; em = 0.f; om = 0.f; op = 0.f; }
                SEp[jb + q][r] = ep; SEm[jb + q][r] = em;
                SOm[jb + q][r] = om; SOp[jb + q][r] = op;
            }
        }
#pragma unroll
        for (int i = 0; i < 2; i++) {   // B tiles: 512 float4
            int f = tid + i * 256;
            int which = f >> 7, gg = f & 127;
            int nl = gg >> 3, c4 = (gg & 7) * 4;
            const float* src =
                (which == 0 ? d_Tce : which == 1 ? d_Tco : which == 2 ? d_Tse : d_Tso)
                + (kc + nl) * 32 + c4;
            float* dst = (which == 0 ? &SCe[nl][c4] : which == 1 ? &SCo[nl][c4]
                        : which == 2 ? &SSe[nl][c4] : &SSo[nl][c4]);
            *(float4*)dst = *(const float4*)src;
        }
        __syncthreads();
        const float* Ap = grp ? &SEm[0][0] : &SEp[0][0];
        const float* Ai = grp ? &SOp[0][0] : &SOm[0][0];
        const float* Bc = grp ? &SCo[0][0] : &SCe[0][0];
        const float* Bs = grp ? &SSo[0][0] : &SSe[0][0];
#pragma unroll
        for (int nl = 0; nl < 16; nl++) {
            float4 e0 = *(const float4*)(Ap + nl * 132 + rg * 8);
            float4 e1 = *(const float4*)(Ap + nl * 132 + rg * 8 + 4);
            float4 q0 = *(const float4*)(Ai + nl * 132 + rg * 8);
            float4 q1 = *(const float4*)(Ai + nl * 132 + rg * 8 + 4);
            float4 bc = *(const float4*)(Bc + nl * 32 + cg * 4);
            float4 bs = *(const float4*)(Bs + nl * 32 + cg * 4);
            float ev[8] = {e0.x,e0.y,e0.z,e0.w,e1.x,e1.y,e1.z,e1.w};
            float ov[8] = {q0.x,q0.y,q0.z,q0.w,q1.x,q1.y,q1.z,q1.w};
            float bcv[4] = {bc.x,bc.y,bc.z,bc.w};
            float bsv[4] = {bs.x,bs.y,bs.z,bs.w};
#pragma unroll
            for (int m = 0; m < 8; m++)
#pragma unroll
                for (int w = 0; w < 4; w++) {
                    aR[m][w] = fmaf(ev[m], bcv[w], aR[m][w]);
                    aI[m][w] = fmaf(ov[m], bsv[w], aI[m][w]);
                }
        }
    }
    // epilogue: boundary terms; float2 (re,im) stores
#pragma unroll
    for (int m = 0; m < 8; m++) {
        long row = row0 + rg * 8 + m;
        const float* xr = x + row * W_;
        float x0 = xr[0], x128 = xr[128], x256 = xr[256], x384 = xr[384];
        float e128 = x128 + x384, o128 = x128 - x384;
        float* Up = d_U + row * 128 + (grp ? 2 : 0);
#pragma unroll
        for (int w = 0; w < 4; w++) {
            int j = cg * 4 + w;
            float re, im;
            if (!grp) {
                re = aR[m][w] + x0 + x256 + ((j & 1) ? -e128 : e128);
                im = aI[m][w];
            } else {
                re = aR[m][w] + x0 - x256;
                im = aI[m][w] + ((j & 1) ? o128 : -o128);
            }
            *(float2*)(Up + 4 * j) = make_float2(re, im);
        }
    }
}

// ---------------- filter (fast-math, float4 LDS) ----------------
__global__ void __launch_bounds__(256) k_filter(
    const float* __restrict__ w, const float* __restrict__ bias,
    const float* __restrict__ dt)
{
    __shared__ float ws[4096];
    __shared__ float bs[64];
    int tid = threadIdx.x;
#pragma unroll
    for (int i = tid; i < 4096; i += 256) ws[i] = w[i];
    if (tid < 64) bs[tid] = bias[tid];
    __syncthreads();

    int id = blockIdx.x * 256 + tid;
    int j = id & 63, h = (id >> 6) & 255, bb = id >> 14;
    float xv[64];
#pragma unroll
    for (int c = 0; c < 64; c++)
        xv[c] = d_xp[(((size_t)(bb * 64 + c)) * 256 + h) * 64 + j];
    float dtb = dt[bb];
    float pdt = 3.14159265358979323846f * dtb;
    float fr = 0.f, fi = 0.f;
    for (int r = 0; r < 32; r++) {
        float p1 = bs[r], p2 = bs[32 + r];
#pragma unroll
        for (int c4 = 0; c4 < 16; c4++) {
            float4 w1 = *(const float4*)&ws[r * 64 + c4 * 4];
            float4 w2 = *(const float4*)&ws[(32 + r) * 64 + c4 * 4];
            p1 = fmaf(w1.x, xv[c4*4+0], p1); p2 = fmaf(w2.x, xv[c4*4+0], p2);
            p1 = fmaf(w1.y, xv[c4*4+1], p1); p2 = fmaf(w2.y, xv[c4*4+1], p2);
            p1 = fmaf(w1.z, xv[c4*4+2], p1); p2 = fmaf(w2.z, xv[c4*4+2], p2);
            p1 = fmaf(w1.w, xv[c4*4+3], p1); p2 = fmaf(w2.w, xv[c4*4+3], p2);
        }
        float nu  = __logf(1.f + __expf(p1));
        float e2  = __expf(2.f * p2);
        float ang = pdt - __fdividef(2.f * pdt, e2 + 1.f);
        float dec = __expf(-nu * dtb);
        float s, co; __sincosf(ang, &s, &co);
        fr = fmaf(dec, co, fr);
        fi = fmaf(dec, s, fi);
    }
    d_G[id] = make_float2((fr - 1.f) * 0.00390625f, fi * 0.00390625f);
}

// ---------------- fused H transform (in-place smem, 20.5KB) ----------------
#define PSTR 9
__global__ void __launch_bounds__(128) k_hfft() {
    __shared__ float SAr[256*PSTR], SAi[256*PSTR];
    __shared__ float2 Ws[256];
    const int bc = blockIdx.x >> 1;
    const int half = blockIdx.x & 1;
    const int b = bc >> 6;
    const int t = threadIdx.x;
    const int kk = t & 7, u = t >> 3;

    for (int i = t; i < 256; i += 128) {
        float2 e = d_E[2 * i];
        Ws[i] = make_float2(e.x, -e.y);
    }
    const float2* Ub = (const float2*)d_U + (size_t)bc * 256 * 64;
    float2*       Vb = (float2*)d_V + (size_t)bc * 256 * 64;

    for (int kb = half * 32; kb < half * 32 + 32; kb += 8) {
        __syncthreads();                    // guard: prev phase-C reads done
        for (int i = t; i < 2048; i += 128) {
            int h = i >> 3, k2 = i & 7;
            float2 uv = Ub[h * 64 + kb + k2];
            SAr[h * PSTR + k2] = uv.x; SAi[h * PSTR + k2] = uv.y;
        }
        __syncthreads();
        float2 v[16];
        // phase A: fwd over n2, in-place transpose via regs
#pragma unroll
        for (int n2 = 0; n2 < 16; n2++) {
            int p = (u + 16 * n2) * PSTR + kk;
            v[n2] = make_float2(SAr[p], SAi[p]);
        }
        fft16<0>(v);
#pragma unroll
        for (int k2 = 1; k2 < 16; k2++) v[k2] = cmul(v[k2], Ws[u * k2]);
        __syncthreads();                    // all reads done before overwrite
#pragma unroll
        for (int k2 = 0; k2 < 16; k2++) {
            int p = (k2 * 16 + u) * PSTR + kk;
            SAr[p] = v[k2].x; SAi[p] = v[k2].y;
        }
        __syncthreads();
        // phase B: fwd stage-2, xG, inv stage-1
#pragma unroll
        for (int n1 = 0; n1 < 16; n1++) {
            int p = (u * 16 + n1) * PSTR + kk;
            v[n1] = make_float2(SAr[p], SAi[p]);
        }
        fft16<0>(v);
#pragma unroll
        for (int r = 0; r < 16; r++) {
            float2 g = d_G[((size_t)b * 256 + u + 16 * r) * 64 + kb + kk];
            v[r] = cmul(v[r], g);
        }
        fft16<1>(v);
        __syncthreads();
#pragma unroll
        for (int n2 = 0; n2 < 16; n2++) {
            float2 wc = Ws[u * n2]; wc.y = -wc.y;
            float2 r = cmul(v[n2], wc);
            int p = (n2 * 16 + u) * PSTR + kk;
            SAr[p] = r.x; SAi[p] = r.y;
        }
        __syncthreads();
        // phase C: inv stage-2, write out
#pragma unroll
        for (int m1 = 0; m1 < 16; m1++) {
            int p = (u * 16 + m1) * PSTR + kk;
            v[m1] = make_float2(SAr[p], SAi[p]);
        }
        fft16<1>(v);
#pragma unroll
        for (int n1 = 0; n1 < 16; n1++)
            Vb[(u + 16 * n1) * 64 + kb + kk] = v[n1];
    }
}

// ---------------- K5 inverse: plane-split + single exchange + fused edge --------
__global__ void __launch_bounds__(256) k_inv(const float* __restrict__ x,
                                             float* __restrict__ out) {
    __shared__ float SM[8960];
    float* VRe = SM;            float* VIe = SM + 1088;
    float* VRo = SM + 2176;     float* VIo = SM + 3264;
    float* BPe = SM + 4352;     float* BPo = SM + 5376;
    float* BQe = SM + 6400;     float* BQo = SM + 7424;
    const int tid = threadIdx.x;
    const int grp = tid >> 7;           // 0: (Pe,Qe)  1: (Po,Qo)
    const int idx = tid & 127;
    const int rg  = idx >> 4;           // 8 row groups x 8 rows
    const int ng  = idx & 15;           // 16 n groups x 4 n
    const long row0 = (long)blockIdx.x * 64;
    const int n0 = blockIdx.y * 64;
    const bool edge = (grp == 0) && (ng == 0) && (n0 == 0);

    float P[8][4], Q[8][4];
    float P128[8], Q128[8];
#pragma unroll
    for (int m = 0; m < 8; m++) {
        P128[m] = 0.f; Q128[m] = 0.f;
#pragma unroll
        for (int w = 0; w < 4; w++) { P[m][w] = 0.f; Q[m][w] = 0.f; }
    }

    for (int jc = 0; jc < 32; jc += 16) {
        __syncthreads();
#pragma unroll
        for (int i = 0; i < 4; i++) {   // V chunk -> 4 planes
            int f = tid + i * 256;
            int r = f >> 4, jl = f & 15;
            float4 v = *(const float4*)&d_V[(row0 + r) * 128 + (jc + jl) * 4];
            VRe[jl * 68 + r] = v.x; VIe[jl * 68 + r] = v.y;
            VRo[jl * 68 + r] = v.z; VIo[jl * 68 + r] = v.w;
        }
#pragma unroll
        for (int i = 0; i < 4; i++) {   // B tables
            int f = tid + i * 256;
            int which = f >> 8, gg = f & 255;
            int jl = gg >> 4, n4 = (gg & 15) * 4;
            const float* src =
                (which == 0 ? d_Ipe : which == 1 ? d_Ipo : which == 2 ? d_Iqe : d_Iqo)
                + (jc + jl) * 128 + n0 + n4;
            float* dst = (which == 0 ? BPe : which == 1 ? BPo
                        : which == 2 ? BQe : BQo) + jl * 64 + n4;
            *(float4*)dst = *(const float4*)src;
        }
        __syncthreads();
        const float* Vr = grp ? VRo : VRe;
        const float* Vi = grp ? VIo : VIe;
        const float* Bp = grp ? BPo : BPe;
        const float* Bq = grp ? BQo : BQe;
#pragma unroll
        for (int jl = 0; jl < 16; jl++) {
            float4 r0 = *(const float4*)(Vr + jl * 68 + rg * 8);
            float4 r1 = *(const float4*)(Vr + jl * 68 + rg * 8 + 4);
            float4 i0 = *(const float4*)(Vi + jl * 68 + rg * 8);
            float4 i1 = *(const float4*)(Vi + jl * 68 + rg * 8 + 4);
            float4 bp = *(const float4*)(Bp + jl * 64 + ng * 4);
            float4 bq = *(const float4*)(Bq + jl * 64 + ng * 4);
            float vr[8] = {r0.x,r0.y,r0.z,r0.w,r1.x,r1.y,r1.z,r1.w};
            float vi[8] = {i0.x,i0.y,i0.z,i0.w,i1.x,i1.y,i1.z,i1.w};
            float pv[4] = {bp.x,bp.y,bp.z,bp.w};
            float qv[4] = {bq.x,bq.y,bq.z,bq.w};
#pragma unroll
            for (int m = 0; m < 8; m++)
#pragma unroll
                for (int w = 0; w < 4; w++) {
                    P[m][w] = fmaf(vr[m], pv[w], P[m][w]);
                    Q[m][w] = fmaf(vi[m], qv[w], Q[m][w]);
                }
        }
        // fused edge columns: n=128 weights (odd-cos & even-sin vanish)
        if (edge) {
            for (int jl = 0; jl < 16; jl++) {
                int j = jc + jl;
                float wE = (j == 0) ? 1.f : ((j & 1) ? -2.f : 2.f);
                float wO = (j & 1) ? -2.f : 2.f;
#pragma unroll
                for (int m = 0; m < 8; m++) {
                    P128[m] = fmaf(VRe[jl * 68 + rg * 8 + m], wE, P128[m]);
                    Q128[m] = fmaf(VIo[jl * 68 + rg * 8 + m], wO, Q128[m]);
                }
            }
        }
    }
    __syncthreads();
    if (grp) {                          // O group ships P,Q through smem
        float* e = SM + idx * 70;
#pragma unroll
        for (int m = 0; m < 8; m++)
#pragma unroll
            for (int w = 0; w < 4; w++) {
                e[m * 4 + w]      = P[m][w];
                e[32 + m * 4 + w] = Q[m][w];
            }
    }
    __syncthreads();
    if (!grp) {                         // E group combines + stores everything
        const float* e = SM + idx * 70;
        const float s = 1.f / 512.f;
#pragma unroll
        for (int m = 0; m < 8; m++) {
            long row = row0 + rg * 8 + m;
            const float* xr = x + row * W_;
            float* orow = out + row * W_;
            int nn0 = n0 + ng * 4;
            float4 xf = *(const float4*)(xr + nn0);
            float4 xg = *(const float4*)(xr + 256 + nn0);
            float d1[4], d2[4], d3[4], d4[4];
#pragma unroll
            for (int w = 0; w < 4; w++) {
                float Po = e[m * 4 + w], Qo = e[32 + m * 4 + w];
                float pp = P[m][w] + Po, pm = P[m][w] - Po;
                float qp = Q[m][w] + Qo, qm = Q[m][w] - Qo;
                d1[w] = pp - qp;    // y[n]
                d2[w] = pp + qp;    // y[512-n]
                d3[w] = pm + qm;    // y[256-n]
                d4[w] = pm - qm;    // y[256+n]
            }
            float4 o1, o2;
            o1.x = fmaf(d1[0], s, xf.x); o1.y = fmaf(d1[1], s, xf.y);
            o1.z = fmaf(d1[2], s, xf.z); o1.w = fmaf(d1[3], s, xf.w);
            o2.x = fmaf(d4[0], s, xg.x); o2.y = fmaf(d4[1], s, xg.y);
            o2.z = fmaf(d4[2], s, xg.z); o2.w = fmaf(d4[3], s, xg.w);
            *(float4*)(orow + nn0) = o1;
            *(float4*)(orow + 256 + nn0) = o2;
            {   // mirror 256-n  (range [129,256])
                int b0 = 256 - nn0;
                orow[b0] = fmaf(d3[0], s, xr[b0]);
                float2 mm = *(const float2*)(xr + b0 - 2);
                *(float2*)(orow + b0 - 2) =
                    make_float2(fmaf(d3[2], s, mm.x), fmaf(d3[1], s, mm.y));
                orow[b0 - 3] = fmaf(d3[3], s, xr[b0 - 3]);
            }
            {   // mirror (512-n)&511 (wrap at nn0=0,w=0 writes same value as o1.x)
                int b0 = (512 - nn0) & 511;
                orow[b0] = fmaf(d2[0], s, xr[b0]);
                int b2 = 510 - nn0;
                float2 mm = *(const float2*)(xr + b2);
                *(float2*)(orow + b2) =
                    make_float2(fmaf(d2[2], s, mm.x), fmaf(d2[1], s, mm.y));
                orow[b2 - 1] = fmaf(d2[3], s, xr[b2 - 1]);
            }
            if (edge) {     // columns 128 & 384 (only n0==0, ng==0 threads)
                out[row * W_ + 128] = fmaf(P128[m] - Q128[m], s, xr[128]);
                out[row * W_ + 384] = fmaf(P128[m] + Q128[m], s, xr[384]);
            }
        }
    }
}

// ---------------- launch ----------------
extern "C" void kernel_launch(void* const* d_in, const int* in_sizes, int n_in,
                              void* d_out, int out_size) {
    const float* x    = (const float*)d_in[0];
    const float* dt   = (const float*)d_in[1];
    const float* w    = (const float*)d_in[2];
    const float* bias = (const float*)d_in[3];
    float* out = (float*)d_out;

    k_tables<<<128, 256>>>();
    k_fwd<<<NROW / 128, 256>>>(x);      // also writes d_xp (fused pooling)
    k_filter<<<B_ * H_ * KF / 256, 256>>>(w, bias, dt);
    k_hfft<<<B_ * C_ * 2, 128>>>();
    k_inv<<<dim3(NROW / 64, 2), 256>>>(x, out);
}

// round 17
// speedup vs baseline: 1.3096x; 1.2676x over previous
#include <cuda_runtime.h>
#include <math.h>

#define B_ 8
#define C_ 64
#define H_ 256
#define W_ 512
#define KF 64
#define NROW (B_*C_*H_)  // 131072 rows

// ---------------- static device scratch (allocation-free rule) ----------------
__device__ __align__(16) float  d_Tce[128 * 32];   // cos(2pi n j/256)        [n][j]
__device__ __align__(16) float  d_Tco[128 * 32];   // cos(pi n (2j+1)/256)    [n][j]
__device__ __align__(16) float  d_Tse[128 * 32];   // -sin(2pi n j/256)       [n][j]
__device__ __align__(16) float  d_Tso[128 * 32];   // -sin(pi n (2j+1)/256)   [n][j]
__device__ __align__(16) float  d_Ipe[32 * 128];   // c2j cos(2pi n j/256)    [j][n]
__device__ __align__(16) float  d_Ipo[32 * 128];   // 2 cos(pi n (2j+1)/256)  [j][n]
__device__ __align__(16) float  d_Iqe[32 * 128];   // c2j sin(2pi n j/256)    [j][n]
__device__ __align__(16) float  d_Iqo[32 * 128];   // 2 sin(pi n (2j+1)/256)  [j][n]
__device__ __align__(16) float2 d_E[W_];           // e^{+2 pi i t/512}
__device__ __align__(16) float  d_xp[(size_t)NROW * KF];
__device__ __align__(16) float2 d_G[B_ * H_ * KF];           // (filt-1)/256
__device__ __align__(16) float  d_U[(size_t)NROW * 2 * KF];  // (b,c,h,k{r,i})
__device__ __align__(16) float  d_V[(size_t)NROW * 2 * KF];  // (b,c,n,k{r,i})

__device__ __forceinline__ float2 cadd(float2 a, float2 b){ return make_float2(a.x+b.x, a.y+b.y); }
__device__ __forceinline__ float2 csub(float2 a, float2 b){ return make_float2(a.x-b.x, a.y-b.y); }
__device__ __forceinline__ float2 cmul(float2 a, float2 b){
    return make_float2(fmaf(a.x,b.x,-a.y*b.y), fmaf(a.x,b.y,a.y*b.x));
}

// ---------------- in-register FFT16 (natural order), INV=0 fwd, 1 inv ----------
template<int INV>
__device__ __forceinline__ void fft16(float2* v) {
    const float C1 = 0.9238795325112867f, S1 = 0.3826834323650898f;
    const float C2 = 0.7071067811865476f;
    const float sg = INV ? 1.f : -1.f;
    const float2 w1 = make_float2( C1, sg*S1);
    const float2 w2 = make_float2( C2, sg*C2);
    const float2 w3 = make_float2( S1, sg*C1);
    const float2 w4 = make_float2(0.f, sg);
    const float2 w6 = make_float2(-C2, sg*C2);
    const float2 w9 = make_float2(-C1, -sg*S1);
    float2 A[16];
#pragma unroll
    for (int n0 = 0; n0 < 4; n0++) {
        float2 a=v[n0], b=v[n0+4], c=v[n0+8], d=v[n0+12];
        float2 t0=cadd(a,c), t1=csub(a,c), t2=cadd(b,d), t3=csub(b,d);
        float2 jt3 = INV ? make_float2(-t3.y, t3.x) : make_float2(t3.y, -t3.x);
        A[n0*4+0]=cadd(t0,t2); A[n0*4+1]=cadd(t1,jt3);
        A[n0*4+2]=csub(t0,t2); A[n0*4+3]=csub(t1,jt3);
    }
    A[5]=cmul(A[5],w1);  A[6]=cmul(A[6],w2);  A[7]=cmul(A[7],w3);
    A[9]=cmul(A[9],w2);  A[10]=cmul(A[10],w4); A[11]=cmul(A[11],w6);
    A[13]=cmul(A[13],w3); A[14]=cmul(A[14],w6); A[15]=cmul(A[15],w9);
#pragma unroll
    for (int k1 = 0; k1 < 4; k1++) {
        float2 a=A[k1], b=A[4+k1], c=A[8+k1], d=A[12+k1];
        float2 t0=cadd(a,c), t1=csub(a,c), t2=cadd(b,d), t3=csub(b,d);
        float2 jt3 = INV ? make_float2(-t3.y, t3.x) : make_float2(t3.y, -t3.x);
        v[k1+0]=cadd(t0,t2); v[k1+4]=cadd(t1,jt3);
        v[k1+8]=csub(t0,t2); v[k1+12]=csub(t1,jt3);
    }
}

// ---------------- tables (float sincospif: args are exact m/256) ----------------
__global__ void k_tables() {
    int t = blockIdx.x * 256 + threadIdx.x;     // 32768
    if (t < 512) {
        float s, c; sincospif((float)t / 256.f, &s, &c);
        d_E[t] = make_float2(c, s);
    }
    int id = t >> 12, idx = t & 4095;
    float s, c;
    if (id < 4) {                               // fwd: idx = n*32 + j
        int n = idx >> 5, j = idx & 31;
        if (id == 0 || id == 2) sincospif((float)((n * j) & 255) / 128.f, &s, &c);
        else                    sincospif((float)((n * (2 * j + 1)) & 511) / 256.f, &s, &c);
        if (id == 0) d_Tce[idx] = c;
        else if (id == 1) d_Tco[idx] = c;
        else if (id == 2) d_Tse[idx] = -s;
        else              d_Tso[idx] = -s;
    } else {                                    // inv: idx = j*128 + n
        int j = idx >> 7, n = idx & 127;
        if (id == 4 || id == 6) sincospif((float)((n * j) & 255) / 128.f, &s, &c);
        else                    sincospif((float)((n * (2 * j + 1)) & 511) / 256.f, &s, &c);
        float ce = (j == 0) ? 1.f : 2.f;
        if (id == 4) d_Ipe[idx] = ce * c;
        else if (id == 5) d_Ipo[idx] = 2.f * c;
        else if (id == 6) d_Iqe[idx] = ce * s;
        else              d_Iqo[idx] = 2.f * s;
    }
}

// ---------------- K1 forward: plane-split groups, 128 rows/block ----------------
__global__ void __launch_bounds__(256) k_fwd(const float* __restrict__ x) {
    __shared__ float SEp[16][132], SEm[16][132], SOm[16][132], SOp[16][132];
    __shared__ float SCe[16][32], SCo[16][32], SSe[16][32], SSo[16][32];
    const int tid = threadIdx.x;
    const long row0 = (long)blockIdx.x * 128;
    const int grp = tid >> 7;           // 0: even k (re_e,im_e), 1: odd k
    const int idx = tid & 127;
    const int rg  = idx >> 3;           // 16 row groups x 8 rows
    const int cg  = idx & 7;            // 8 col groups x 4 j

    float aR[8][4], aI[8][4];
#pragma unroll
    for (int m = 0; m < 8; m++)
#pragma unroll
        for (int w = 0; w < 4; w++) { aR[m][w] = 0.f; aI[m][w] = 0.f; }

    const int r = tid >> 1;             // 0..127 row for A-phase
    const int half = tid & 1;
    const float* xp = x + (row0 + r) * W_;
    float* xpr = d_xp + (row0 + r) * 64;

    for (int kc = 0; kc < 128; kc += 16) {
        __syncthreads();
        {   // A-phase fold + fused pooling (8-aligned, no shuffles)
            int o = kc + half * 8;
            float4 a0 = *(const float4*)(xp + o);
            float4 a1 = *(const float4*)(xp + o + 4);
            float4 c0 = *(const float4*)(xp + 256 + o);
            float4 c1 = *(const float4*)(xp + 260 + o);
            float4 bl = *(const float4*)(xp + 248 - o);
            float4 bh = *(const float4*)(xp + 252 - o);
            float4 dl = *(const float4*)(xp + 504 - o);
            float4 dh = *(const float4*)(xp + 508 - o);
            float  bsc = xp[256 - o];
            float  dsc = xp[(512 - o) & 511];
            int g = o >> 3;
            xpr[g]      = ((a0.x+a0.y)+(a0.z+a0.w)+(a1.x+a1.y)+(a1.z+a1.w))*0.125f;
            xpr[31 - g] = ((bl.x+bl.y)+(bl.z+bl.w)+(bh.x+bh.y)+(bh.z+bh.w))*0.125f;
            xpr[32 + g] = ((c0.x+c0.y)+(c0.z+c0.w)+(c1.x+c1.y)+(c1.z+c1.w))*0.125f;
            xpr[63 - g] = ((dl.x+dl.y)+(dl.z+dl.w)+(dh.x+dh.y)+(dh.z+dh.w))*0.125f;
            float aq[8] = {a0.x,a0.y,a0.z,a0.w,a1.x,a1.y,a1.z,a1.w};
            float cq[8] = {c0.x,c0.y,c0.z,c0.w,c1.x,c1.y,c1.z,c1.w};
            float bq[8] = {bsc,bh.w,bh.z,bh.y,bh.x,bl.w,bl.z,bl.y};
            float dq[8] = {dsc,dh.w,dh.z,dh.y,dh.x,dl.w,dl.z,dl.y};
            int jb = half * 8;
#pragma unroll
            for (int q = 0; q < 8; q++) {
                float sa = aq[q] + dq[q], da = aq[q] - dq[q];
                float sb = bq[q] + cq[q], db = bq[q] - cq[q];
                float ep = sa + sb, em = sa - sb, om = da - db, op = da + db;
                if (o + q == 0) { ep = 0.f; em = 0.f; om = 0.f; op = 0.f; }
                SEp[jb + q][r] = ep; SEm[jb + q][r] = em;
                SOm[jb + q][r] = om; SOp[jb + q][r] = op;
            }
        }
#pragma unroll
        for (int i = 0; i < 2; i++) {   // B tiles: 512 float4
            int f = tid + i * 256;
            int which = f >> 7, gg = f & 127;
            int nl = gg >> 3, c4 = (gg & 7) * 4;
            const float* src =
                (which == 0 ? d_Tce : which == 1 ? d_Tco : which == 2 ? d_Tse : d_Tso)
                + (kc + nl) * 32 + c4;
            float* dst = (which == 0 ? &SCe[nl][c4] : which == 1 ? &SCo[nl][c4]
                        : which == 2 ? &SSe[nl][c4] : &SSo[nl][c4]);
            *(float4*)dst = *(const float4*)src;
        }
        __syncthreads();
        const float* Ap = grp ? &SEm[0][0] : &SEp[0][0];
        const float* Ai = grp ? &SOp[0][0] : &SOm[0][0];
        const float* Bc = grp ? &SCo[0][0] : &SCe[0][0];
        const float* Bs = grp ? &SSo[0][0] : &SSe[0][0];
#pragma unroll
        for (int nl = 0; nl < 16; nl++) {
            float4 e0 = *(const float4*)(Ap + nl * 132 + rg * 8);
            float4 e1 = *(const float4*)(Ap + nl * 132 + rg * 8 + 4);
            float4 q0 = *(const float4*)(Ai + nl * 132 + rg * 8);
            float4 q1 = *(const float4*)(Ai + nl * 132 + rg * 8 + 4);
            float4 bc = *(const float4*)(Bc + nl * 32 + cg * 4);
            float4 bs = *(const float4*)(Bs + nl * 32 + cg * 4);
            float ev[8] = {e0.x,e0.y,e0.z,e0.w,e1.x,e1.y,e1.z,e1.w};
            float ov[8] = {q0.x,q0.y,q0.z,q0.w,q1.x,q1.y,q1.z,q1.w};
            float bcv[4] = {bc.x,bc.y,bc.z,bc.w};
            float bsv[4] = {bs.x,bs.y,bs.z,bs.w};
#pragma unroll
            for (int m = 0; m < 8; m++)
#pragma unroll
                for (int w = 0; w < 4; w++) {
                    aR[m][w] = fmaf(ev[m], bcv[w], aR[m][w]);
                    aI[m][w] = fmaf(ov[m], bsv[w], aI[m][w]);
                }
        }
    }
    // epilogue: boundary terms; float2 (re,im) stores
#pragma unroll
    for (int m = 0; m < 8; m++) {
        long row = row0 + rg * 8 + m;
        const float* xr = x + row * W_;
        float x0 = xr[0], x128 = xr[128], x256 = xr[256], x384 = xr[384];
        float e128 = x128 + x384, o128 = x128 - x384;
        float* Up = d_U + row * 128 + (grp ? 2 : 0);
#pragma unroll
        for (int w = 0; w < 4; w++) {
            int j = cg * 4 + w;
            float re, im;
            if (!grp) {
                re = aR[m][w] + x0 + x256 + ((j & 1) ? -e128 : e128);
                im = aI[m][w];
            } else {
                re = aR[m][w] + x0 - x256;
                im = aI[m][w] + ((j & 1) ? o128 : -o128);
            }
            *(float2*)(Up + 4 * j) = make_float2(re, im);
        }
    }
}

// ---------------- filter (fast-math, float4 LDS) ----------------
__global__ void __launch_bounds__(256) k_filter(
    const float* __restrict__ w, const float* __restrict__ bias,
    const float* __restrict__ dt)
{
    __shared__ float ws[4096];
    __shared__ float bs[64];
    int tid = threadIdx.x;
#pragma unroll
    for (int i = tid; i < 4096; i += 256) ws[i] = w[i];
    if (tid < 64) bs[tid] = bias[tid];
    __syncthreads();

    int id = blockIdx.x * 256 + tid;
    int j = id & 63, h = (id >> 6) & 255, bb = id >> 14;
    float xv[64];
#pragma unroll
    for (int c = 0; c < 64; c++)
        xv[c] = d_xp[(((size_t)(bb * 64 + c)) * 256 + h) * 64 + j];
    float dtb = dt[bb];
    float pdt = 3.14159265358979323846f * dtb;
    float fr = 0.f, fi = 0.f;
    for (int r = 0; r < 32; r++) {
        float p1 = bs[r], p2 = bs[32 + r];
#pragma unroll
        for (int c4 = 0; c4 < 16; c4++) {
            float4 w1 = *(const float4*)&ws[r * 64 + c4 * 4];
            float4 w2 = *(const float4*)&ws[(32 + r) * 64 + c4 * 4];
            p1 = fmaf(w1.x, xv[c4*4+0], p1); p2 = fmaf(w2.x, xv[c4*4+0], p2);
            p1 = fmaf(w1.y, xv[c4*4+1], p1); p2 = fmaf(w2.y, xv[c4*4+1], p2);
            p1 = fmaf(w1.z, xv[c4*4+2], p1); p2 = fmaf(w2.z, xv[c4*4+2], p2);
            p1 = fmaf(w1.w, xv[c4*4+3], p1); p2 = fmaf(w2.w, xv[c4*4+3], p2);
        }
        float nu  = __logf(1.f + __expf(p1));
        float e2  = __expf(2.f * p2);
        float ang = pdt - __fdividef(2.f * pdt, e2 + 1.f);
        float dec = __expf(-nu * dtb);
        float s, co; __sincosf(ang, &s, &co);
        fr = fmaf(dec, co, fr);
        fi = fmaf(dec, s, fi);
    }
    d_G[id] = make_float2((fr - 1.f) * 0.00390625f, fi * 0.00390625f);
}

// ---------------- fused H transform (in-place smem, 20.5KB) ----------------
#define PSTR 9
__global__ void __launch_bounds__(128) k_hfft() {
    __shared__ float SAr[256*PSTR], SAi[256*PSTR];
    __shared__ float2 Ws[256];
    const int bc = blockIdx.x >> 1;
    const int half = blockIdx.x & 1;
    const int b = bc >> 6;
    const int t = threadIdx.x;
    const int kk = t & 7, u = t >> 3;

    for (int i = t; i < 256; i += 128) {
        float2 e = d_E[2 * i];
        Ws[i] = make_float2(e.x, -e.y);
    }
    const float2* Ub = (const float2*)d_U + (size_t)bc * 256 * 64;
    float2*       Vb = (float2*)d_V + (size_t)bc * 256 * 64;

    for (int kb = half * 32; kb < half * 32 + 32; kb += 8) {
        __syncthreads();                    // guard: prev phase-C reads done
        for (int i = t; i < 2048; i += 128) {
            int h = i >> 3, k2 = i & 7;
            float2 uv = Ub[h * 64 + kb + k2];
            SAr[h * PSTR + k2] = uv.x; SAi[h * PSTR + k2] = uv.y;
        }
        __syncthreads();
        float2 v[16];
        // phase A: fwd over n2, in-place transpose via regs
#pragma unroll
        for (int n2 = 0; n2 < 16; n2++) {
            int p = (u + 16 * n2) * PSTR + kk;
            v[n2] = make_float2(SAr[p], SAi[p]);
        }
        fft16<0>(v);
#pragma unroll
        for (int k2 = 1; k2 < 16; k2++) v[k2] = cmul(v[k2], Ws[u * k2]);
        __syncthreads();                    // all reads done before overwrite
#pragma unroll
        for (int k2 = 0; k2 < 16; k2++) {
            int p = (k2 * 16 + u) * PSTR + kk;
            SAr[p] = v[k2].x; SAi[p] = v[k2].y;
        }
        __syncthreads();
        // phase B: fwd stage-2, xG, inv stage-1
#pragma unroll
        for (int n1 = 0; n1 < 16; n1++) {
            int p = (u * 16 + n1) * PSTR + kk;
            v[n1] = make_float2(SAr[p], SAi[p]);
        }
        fft16<0>(v);
#pragma unroll
        for (int r = 0; r < 16; r++) {
            float2 g = d_G[((size_t)b * 256 + u + 16 * r) * 64 + kb + kk];
            v[r] = cmul(v[r], g);
        }
        fft16<1>(v);
        __syncthreads();
#pragma unroll
        for (int n2 = 0; n2 < 16; n2++) {
            float2 wc = Ws[u * n2]; wc.y = -wc.y;
            float2 r = cmul(v[n2], wc);
            int p = (n2 * 16 + u) * PSTR + kk;
            SAr[p] = r.x; SAi[p] = r.y;
        }
        __syncthreads();
        // phase C: inv stage-2, write out
#pragma unroll
        for (int m1 = 0; m1 < 16; m1++) {
            int p = (u * 16 + m1) * PSTR + kk;
            v[m1] = make_float2(SAr[p], SAi[p]);
        }
        fft16<1>(v);
#pragma unroll
        for (int n1 = 0; n1 < 16; n1++)
            Vb[(u + 16 * n1) * 64 + kb + kk] = v[n1];
    }
}

// ---------------- K5 inverse: plane-split + single exchange + smem edge ---------
__global__ void __launch_bounds__(256) k_inv(const float* __restrict__ x,
                                             float* __restrict__ out) {
    __shared__ float SM[8960];
    __shared__ float Sedge[128];        // [0:64) P128 by row, [64:128) Q128
    float* VRe = SM;            float* VIe = SM + 1088;
    float* VRo = SM + 2176;     float* VIo = SM + 3264;
    float* BPe = SM + 4352;     float* BPo = SM + 5376;
    float* BQe = SM + 6400;     float* BQo = SM + 7424;
    const int tid = threadIdx.x;
    const int grp = tid >> 7;           // 0: (Pe,Qe)  1: (Po,Qo)
    const int idx = tid & 127;
    const int rg  = idx >> 4;           // 8 row groups x 8 rows
    const int ng  = idx & 15;           // 16 n groups x 4 n
    const long row0 = (long)blockIdx.x * 64;
    const int n0 = blockIdx.y * 64;
    const bool edge = (grp == 0) && (ng == 0) && (n0 == 0);

    if (edge) {                         // zero this thread's 16 smem slots
        for (int m = 0; m < 8; m++) {
            Sedge[rg * 8 + m] = 0.f;
            Sedge[64 + rg * 8 + m] = 0.f;
        }
    }

    float P[8][4], Q[8][4];
#pragma unroll
    for (int m = 0; m < 8; m++)
#pragma unroll
        for (int w = 0; w < 4; w++) { P[m][w] = 0.f; Q[m][w] = 0.f; }

    for (int jc = 0; jc < 32; jc += 16) {
        __syncthreads();
#pragma unroll
        for (int i = 0; i < 4; i++) {   // V chunk -> 4 planes
            int f = tid + i * 256;
            int r = f >> 4, jl = f & 15;
            float4 v = *(const float4*)&d_V[(row0 + r) * 128 + (jc + jl) * 4];
            VRe[jl * 68 + r] = v.x; VIe[jl * 68 + r] = v.y;
            VRo[jl * 68 + r] = v.z; VIo[jl * 68 + r] = v.w;
        }
#pragma unroll
        for (int i = 0; i < 4; i++) {   // B tables
            int f = tid + i * 256;
            int which = f >> 8, gg = f & 255;
            int jl = gg >> 4, n4 = (gg & 15) * 4;
            const float* src =
                (which == 0 ? d_Ipe : which == 1 ? d_Ipo : which == 2 ? d_Iqe : d_Iqo)
                + (jc + jl) * 128 + n0 + n4;
            float* dst = (which == 0 ? BPe : which == 1 ? BPo
                        : which == 2 ? BQe : BQo) + jl * 64 + n4;
            *(float4*)dst = *(const float4*)src;
        }
        __syncthreads();
        const float* Vr = grp ? VRo : VRe;
        const float* Vi = grp ? VIo : VIe;
        const float* Bp = grp ? BPo : BPe;
        const float* Bq = grp ? BQo : BQe;
#pragma unroll
        for (int jl = 0; jl < 16; jl++) {
            float4 r0 = *(const float4*)(Vr + jl * 68 + rg * 8);
            float4 r1 = *(const float4*)(Vr + jl * 68 + rg * 8 + 4);
            float4 i0 = *(const float4*)(Vi + jl * 68 + rg * 8);
            float4 i1 = *(const float4*)(Vi + jl * 68 + rg * 8 + 4);
            float4 bp = *(const float4*)(Bp + jl * 64 + ng * 4);
            float4 bq = *(const float4*)(Bq + jl * 64 + ng * 4);
            float vr[8] = {r0.x,r0.y,r0.z,r0.w,r1.x,r1.y,r1.z,r1.w};
            float vi[8] = {i0.x,i0.y,i0.z,i0.w,i1.x,i1.y,i1.z,i1.w};
            float pv[4] = {bp.x,bp.y,bp.z,bp.w};
            float qv[4] = {bq.x,bq.y,bq.z,bq.w};
#pragma unroll
            for (int m = 0; m < 8; m++)
#pragma unroll
                for (int w = 0; w < 4; w++) {
                    P[m][w] = fmaf(vr[m], pv[w], P[m][w]);
                    Q[m][w] = fmaf(vi[m], qv[w], Q[m][w]);
                }
        }
        // fused edge: accumulate in smem (no persistent registers)
        if (edge) {
            for (int jl = 0; jl < 16; jl++) {
                int j = jc + jl;
                float wE = (j == 0) ? 1.f : ((j & 1) ? -2.f : 2.f);
                float wO = (j & 1) ? -2.f : 2.f;
                for (int m = 0; m < 8; m++) {
                    Sedge[rg * 8 + m] =
                        fmaf(VRe[jl * 68 + rg * 8 + m], wE, Sedge[rg * 8 + m]);
                    Sedge[64 + rg * 8 + m] =
                        fmaf(VIo[jl * 68 + rg * 8 + m], wO, Sedge[64 + rg * 8 + m]);
                }
            }
        }
    }
    __syncthreads();
    if (grp) {                          // O group ships P,Q through smem
        float* e = SM + idx * 70;
#pragma unroll
        for (int m = 0; m < 8; m++)
#pragma unroll
            for (int w = 0; w < 4; w++) {
                e[m * 4 + w]      = P[m][w];
                e[32 + m * 4 + w] = Q[m][w];
            }
    }
    __syncthreads();
    if (!grp) {                         // E group combines + stores everything
        const float* e = SM + idx * 70;
        const float s = 1.f / 512.f;
#pragma unroll
        for (int m = 0; m < 8; m++) {
            long row = row0 + rg * 8 + m;
            const float* xr = x + row * W_;
            float* orow = out + row * W_;
            int nn0 = n0 + ng * 4;
            float4 xf = *(const float4*)(xr + nn0);
            float4 xg = *(const float4*)(xr + 256 + nn0);
            float d1[4], d2[4], d3[4], d4[4];
#pragma unroll
            for (int w = 0; w < 4; w++) {
                float Po = e[m * 4 + w], Qo = e[32 + m * 4 + w];
                float pp = P[m][w] + Po, pm = P[m][w] - Po;
                float qp = Q[m][w] + Qo, qm = Q[m][w] - Qo;
                d1[w] = pp - qp;    // y[n]
                d2[w] = pp + qp;    // y[512-n]
                d3[w] = pm + qm;    // y[256-n]
                d4[w] = pm - qm;    // y[256+n]
            }
            float4 o1, o2;
            o1.x = fmaf(d1[0], s, xf.x); o1.y = fmaf(d1[1], s, xf.y);
            o1.z = fmaf(d1[2], s, xf.z); o1.w = fmaf(d1[3], s, xf.w);
            o2.x = fmaf(d4[0], s, xg.x); o2.y = fmaf(d4[1], s, xg.y);
            o2.z = fmaf(d4[2], s, xg.z); o2.w = fmaf(d4[3], s, xg.w);
            *(float4*)(orow + nn0) = o1;
            *(float4*)(orow + 256 + nn0) = o2;
            {   // mirror 256-n  (range [129,256])
                int b0 = 256 - nn0;
                orow[b0] = fmaf(d3[0], s, xr[b0]);
                float2 mm = *(const float2*)(xr + b0 - 2);
                *(float2*)(orow + b0 - 2) =
                    make_float2(fmaf(d3[2], s, mm.x), fmaf(d3[1], s, mm.y));
                orow[b0 - 3] = fmaf(d3[3], s, xr[b0 - 3]);
            }
            {   // mirror (512-n)&511 (wrap at nn0=0,w=0 writes same value as o1.x)
                int b0 = (512 - nn0) & 511;
                orow[b0] = fmaf(d2[0], s, xr[b0]);
                int b2 = 510 - nn0;
                float2 mm = *(const float2*)(xr + b2);
                *(float2*)(orow + b2) =
                    make_float2(fmaf(d2[2], s, mm.x), fmaf(d2[1], s, mm.y));
                orow[b2 - 1] = fmaf(d2[3], s, xr[b2 - 1]);
            }
            if (edge) {     // columns 128 & 384 from smem accumulators
                float pe128 = Sedge[rg * 8 + m];
                float qo128 = Sedge[64 + rg * 8 + m];
                out[row * W_ + 128] = fmaf(pe128 - qo128, s, xr[128]);
                out[row * W_ + 384] = fmaf(pe128 + qo128, s, xr[384]);
            }
        }
    }
}

// ---------------- launch ----------------
extern "C" void kernel_launch(void* const* d_in, const int* in_sizes, int n_in,
                              void* d_out, int out_size) {
    const float* x    = (const float*)d_in[0];
    const float* dt   = (const float*)d_in[1];
    const float* w    = (const float*)d_in[2];
    const float* bias = (const float*)d_in[3];
    float* out = (float*)d_out;

    k_tables<<<128, 256>>>();
    k_fwd<<<NROW / 128, 256>>>(x);      // also writes d_xp (fused pooling)
    k_filter<<<B_ * H_ * KF / 256, 256>>>(w, bias, dt);
    k_hfft<<<B_ * C_ * 2, 128>>>();
    k_inv<<<dim3(NROW / 64, 2), 256>>>(x, out);
}